// round 16
// baseline (speedup 1.0000x reference)
#include <cuda_runtime.h>
#include <cstdint>

#define N_ANCH   300000
#define N_CLS    80
#define DET_DIM  85
#define TOPK     1000
#define MAXBOX   300
#define CAP      4096
#define NMS_THR  0.4f

#define NCH16    (N_ANCH / 16)          // 18750
#define NBLK1    ((NCH16 + 15) / 16)    // 1172 K1 blocks
#define NU4      (N_ANCH / 4)           // 75000 uint4 keys
#define PBLK     256
#define NPASS    ((NU4 + PBLK - 1) / PBLK)       // 293
#define NCBLK    ((NU4 + 1023) / 1024)           // 74 (compact, 1024-thr blocks)
#define NMBLK    ((32 * TOPK + PBLK - 1) / PBLK) // 125 (mask)

// ---------------- device scratch ----------------
__device__ unsigned int       g_scores[N_ANCH];
__device__ unsigned int       g_h1[256];       // bits[31:24]   (zeroed by K7)
__device__ unsigned int       g_h64k[65536];   // bits[23:8]|d1 (zeroed by K6)
__device__ int                g_cand_cnt;      // zeroed by K7
__device__ unsigned long long g_cand[CAP];
__device__ int                g_topk_idx[TOPK];
__device__ float4             g_boxk[TOPK];
__device__ unsigned int       g_maskmat[32 * TOPK];   // TRANSPOSED [colword][row]

__device__ __forceinline__ void aggInc(unsigned int* h, unsigned int bucket) {
    unsigned int am = __activemask();
    unsigned int peers = __match_any_sync(am, bucket);
    int leader = __ffs(peers) - 1;
    if ((threadIdx.x & 31) == leader) atomicAdd(&h[bucket], __popc(peers));
}

// 256-bin resolve (verified; callable with blockDim >= 256)
__device__ __forceinline__ void resolve256(const unsigned int* gh, unsigned int kth,
                                           unsigned int* shR,
                                           unsigned int* s_dig, unsigned int* s_kth) {
    int t = threadIdx.x;
    if (t < 256) shR[t] = gh[t];
    __syncthreads();
    for (int off = 1; off < 256; off <<= 1) {
        unsigned int v = 0, u = 0;
        if (t < 256) { v = shR[t]; u = (t + off < 256) ? shR[t + off] : 0u; }
        __syncthreads();
        if (t < 256) shR[t] = v + u;
        __syncthreads();
    }
    if (t < 256) {
        unsigned int e = (t < 255) ? shR[t + 1] : 0u;
        if (e < kth && shR[t] >= kth) { *s_dig = (unsigned int)t; *s_kth = kth - e; }
    }
    __syncthreads();
}

// 65536-bin resolve, two-stage suffix scan (verified R2/R11); needs 1024 threads
__device__ __forceinline__ void resolve64k(const unsigned int* gh, unsigned int kth,
                                           unsigned int* suf, unsigned int* win64,
                                           int* s_win, unsigned int* s_dig) {
    int t = threadIdx.x;
    unsigned int s = 0;
    const uint4* hp = (const uint4*)gh;
#pragma unroll
    for (int i = 0; i < 16; i++) {
        uint4 v = hp[t * 16 + i];
        s += v.x + v.y + v.z + v.w;
    }
    suf[t] = s;
    __syncthreads();
    for (int off = 1; off < 1024; off <<= 1) {
        unsigned int a = suf[t];
        unsigned int b = (t + off < 1024) ? suf[t + off] : 0u;
        __syncthreads();
        suf[t] = a + b;
        __syncthreads();
    }
    unsigned int excl = (t < 1023) ? suf[t + 1] : 0u;
    if (excl < kth && suf[t] >= kth) *s_win = t;
    __syncthreads();
    int w = *s_win;
    unsigned int wexcl = (w < 1023) ? suf[w + 1] : 0u;
    if (t < 64) win64[t] = gh[w * 64 + t];
    __syncthreads();
    for (int off = 1; off < 64; off <<= 1) {
        unsigned int a = 0, b = 0;
        if (t < 64) { a = win64[t]; b = (t + off < 64) ? win64[t + off] : 0u; }
        __syncthreads();
        if (t < 64) win64[t] = a + b;
        __syncthreads();
    }
    if (t < 64) {
        unsigned int e = wexcl + ((t < 63) ? win64[t + 1] : 0u);
        unsigned int inc = wexcl + win64[t];
        if (e < kth && inc >= kth) *s_dig = (unsigned int)(w * 64 + t);
    }
    __syncthreads();
}

__device__ __forceinline__ float max20(const float4* r) {
    float a0 = fmaxf(fmaxf(r[0].x, r[0].y), fmaxf(r[0].z, r[0].w));
    float a1 = fmaxf(fmaxf(r[1].x, r[1].y), fmaxf(r[1].z, r[1].w));
    float a2 = fmaxf(fmaxf(r[2].x, r[2].y), fmaxf(r[2].z, r[2].w));
    float a3 = fmaxf(fmaxf(r[3].x, r[3].y), fmaxf(r[3].z, r[3].w));
    float a4 = fmaxf(fmaxf(r[4].x, r[4].y), fmaxf(r[4].z, r[4].w));
    return fmaxf(fmaxf(fmaxf(a0, a1), fmaxf(a2, a3)), a4);
}

// ===== K1: score/max (+ldcs) + hist bits[31:24] (proven ~9us warm) =====
extern "C" __global__ void __launch_bounds__(256, 4)
k1_score(const float* __restrict__ cls) {
    __shared__ unsigned int shH[256];
    const int t = threadIdx.x, lane = t & 31, warp = t >> 5;
    shH[t] = 0u;
    __syncthreads();
    const float4* gp = (const float4*)cls;
    const int p = lane & 3, a = lane >> 2;
    const int cend = min((int)((blockIdx.x + 1) * 16), NCH16);
    for (int chunk = blockIdx.x * 16 + warp; chunk < cend; chunk += 8) {
        const size_t b0 = (size_t)chunk * (16 * 20);
        float4 r0[5], r1[5];
        const size_t o0 = b0 + a * 20 + p;
        const size_t o1 = o0 + 160;
#pragma unroll
        for (int j = 0; j < 5; j++) r0[j] = __ldcs(&gp[o0 + 4 * j]);
#pragma unroll
        for (int j = 0; j < 5; j++) r1[j] = __ldcs(&gp[o1 + 4 * j]);
        float m0 = max20(r0), m1 = max20(r1);
        m0 = fmaxf(m0, __shfl_xor_sync(0xFFFFFFFFu, m0, 1));
        m0 = fmaxf(m0, __shfl_xor_sync(0xFFFFFFFFu, m0, 2));
        m1 = fmaxf(m1, __shfl_xor_sync(0xFFFFFFFFu, m1, 1));
        m1 = fmaxf(m1, __shfl_xor_sync(0xFFFFFFFFu, m1, 2));
        unsigned int k0 = __float_as_uint(m0);   // scores >= 0 -> monotonic bits
        unsigned int k1 = __float_as_uint(m1);
        if (p == 0) {
            int A0 = chunk * 16;
            g_scores[A0 + a]     = k0;
            g_scores[A0 + 8 + a] = k1;
            aggInc(shH, k0 >> 24);
            aggInc(shH, k1 >> 24);
        }
    }
    __syncthreads();
    if (shH[t]) atomicAdd(&g_h1[t], shH[t]);
}

// ===== K2: 64K-bin hist over bits[23:8], restricted to d1 =====
extern "C" __global__ void __launch_bounds__(PBLK)
k2_hist64() {
    __shared__ unsigned int shR[256];
    __shared__ unsigned int s_d1, s_k1;
    int t = threadIdx.x;
    resolve256(g_h1, TOPK, shR, &s_d1, &s_k1);
    unsigned int d1 = s_d1;
    int i = blockIdx.x * PBLK + t;
    if (i < NU4) {
        uint4 k = ((const uint4*)g_scores)[i];
        if ((k.x >> 24) == d1) aggInc(g_h64k, (k.x >> 8) & 65535u);
        if ((k.y >> 24) == d1) aggInc(g_h64k, (k.y >> 8) & 65535u);
        if ((k.z >> 24) == d1) aggInc(g_h64k, (k.z >> 8) & 65535u);
        if ((k.w >> 24) == d1) aggInc(g_h64k, (k.w >> 8) & 65535u);
    }
}

// ===== K4: resolve threshold (8b + 16b) + warp-aggregated compact =====
extern "C" __global__ void __launch_bounds__(1024)
k4_compact() {
    __shared__ unsigned int shR[256];
    __shared__ unsigned int suf[1024];
    __shared__ unsigned int win64[64];
    __shared__ int s_win;
    __shared__ unsigned int s_d1, s_k1, s_dig;
    int t = threadIdx.x;
    resolve256(g_h1, TOPK, shR, &s_d1, &s_k1);
    resolve64k(g_h64k, s_k1, suf, win64, &s_win, &s_dig);
    unsigned int T = (s_d1 << 24) | (s_dig << 8);
    int i = blockIdx.x * 1024 + t;
    if (i < NU4) {
        uint4 k = ((const uint4*)g_scores)[i];
        unsigned int bi = (unsigned int)(i * 4);
#pragma unroll
        for (int c = 0; c < 4; c++) {
            unsigned int key = (c == 0) ? k.x : (c == 1) ? k.y : (c == 2) ? k.z : k.w;
            bool p = (key >= T);
            unsigned int am = __activemask();
            unsigned int bal = __ballot_sync(am, p);
            if (p) {
                int lane = t & 31;
                int leader = __ffs(bal) - 1;
                int base = 0;
                if (lane == leader) base = atomicAdd(&g_cand_cnt, __popc(bal));
                base = __shfl_sync(bal, base, leader);
                int slot = base + __popc(bal & ((1u << lane) - 1u));
                if (slot < CAP)
                    g_cand[slot] = ((unsigned long long)key << 32) |
                                   (unsigned long long)(0xFFFFFFFFu - (bi + c));
            }
        }
    }
}

// ===== K5: rank-select (exact stable top-k; unique keys) + box gather =====
extern "C" __global__ void __launch_bounds__(1024)
k5_rank(const float* __restrict__ boxes) {
    __shared__ unsigned long long sc[CAP];
    int t = threadIdx.x;
    int cnt = g_cand_cnt;
    if (cnt > CAP) cnt = CAP;
    for (int i = t; i < cnt; i += 1024) sc[i] = g_cand[i];
    __syncthreads();
    int i = blockIdx.x * 1024 + t;
    if (i < cnt) {
        unsigned long long key = sc[i];
        int rank = 0;
        for (int j = 0; j < cnt; j++) rank += (sc[j] > key);
        if (rank < TOPK) {
            int idx = (int)(0xFFFFFFFFu - (unsigned int)key);
            g_topk_idx[rank] = idx;
            g_boxk[rank] = ((const float4*)boxes)[idx];
        }
    }
}

// ===== K6: IoU bitmask, transposed (bit-exact fp32, verified) + h64k cleanup =====
extern "C" __global__ void __launch_bounds__(PBLK)
k6_mask() {
    int w = blockIdx.x * PBLK + threadIdx.x;
    if (w < 32 * TOPK) {
        int wj = w / TOPK;
        int i  = w - wj * TOPK;
        float4 bi = g_boxk[i];
        float ai = __fmul_rn(__fsub_rn(bi.z, bi.x), __fsub_rn(bi.w, bi.y));
        unsigned int bits = 0u;
        int j0 = wj * 32;
#pragma unroll 8
        for (int tt = 0; tt < 32; tt++) {
            int j = j0 + tt;
            if (j < TOPK) {
                float4 bj = g_boxk[j];
                float aj = __fmul_rn(__fsub_rn(bj.z, bj.x), __fsub_rn(bj.w, bj.y));
                float ih = fmaxf(__fsub_rn(fminf(bi.z, bj.z), fmaxf(bi.x, bj.x)), 0.0f);
                float iw = fmaxf(__fsub_rn(fminf(bi.w, bj.w), fmaxf(bi.y, bj.y)), 0.0f);
                float inter = __fmul_rn(ih, iw);
                float denom = __fadd_rn(__fsub_rn(__fadd_rn(ai, aj), inter), 1e-8f);
                float iou = __fdiv_rn(inter, denom);
                if (iou > NMS_THR) bits |= (1u << tt);
            }
        }
        g_maskmat[w] = bits;
    }
    // zero g_h64k for next replay (65536 words over NMBLK blocks)
    {
        const int seg = (65536 + NMBLK - 1) / NMBLK;   // 525
        int lo = blockIdx.x * seg;
        int hi = min(lo + seg, 65536);
        for (int i2 = lo + threadIdx.x; i2 < hi; i2 += PBLK) g_h64k[i2] = 0u;
    }
}

// ===== K7: single-block greedy keep-scan + output + state cleanup (verified) =====
extern "C" __global__ void __launch_bounds__(1024)
k7_scan(const float* __restrict__ det, float* __restrict__ out) {
    extern __shared__ unsigned int smask[];   // 32*TOPK words
    __shared__ unsigned int keepw[32], wpref[32];
    __shared__ int s_sel[MAXBOX];
    __shared__ int s_nkeep;
    const int t = threadIdx.x, lane = t & 31;
    for (int i = t; i < 32 * TOPK; i += 1024) smask[i] = g_maskmat[i];
    if (t < 256) g_h1[t] = 0u;
    if (t == 0) g_cand_cnt = 0;
    __syncthreads();

    if (t < 32) {
        for (int tile = 0; tile < 32; tile++) {
            int r = tile * 32 + lane;
            int nrows = TOPK - tile * 32; if (nrows > 32) nrows = 32;
            bool base_i = false;
            unsigned int wt_i = 0u;
            if (r < TOPK) {
                for (int w = 0; w < tile; w++)
                    base_i |= (keepw[w] & smask[w * TOPK + r]) != 0u;
                wt_i = smask[tile * TOPK + r];
            }
            unsigned int bases = __ballot_sync(0xFFFFFFFFu, base_i);
            unsigned int keep_tile = 0u;
#pragma unroll
            for (int rr = 0; rr < 32; rr++) {
                unsigned int word_r = __shfl_sync(0xFFFFFFFFu, wt_i, rr);
                bool sup = ((bases >> rr) & 1u) ||
                           ((keep_tile & word_r & ((1u << rr) - 1u)) != 0u);
                if (!sup && rr < nrows) keep_tile |= 1u << rr;
            }
            if (lane == 0) keepw[tile] = keep_tile;
            __syncwarp();
        }
        unsigned int kw = keepw[lane];
        unsigned int pc = __popc(kw);
        unsigned int inc = pc;
        for (int off = 1; off < 32; off <<= 1) {
            unsigned int v = __shfl_up_sync(0xFFFFFFFFu, inc, off);
            if (lane >= off) inc += v;
        }
        wpref[lane] = inc - pc;
        if (lane == 31) s_nkeep = (int)inc;
    }
    __syncthreads();

    if (t < TOPK) {
        int w = t >> 5, b = t & 31;
        unsigned int kw = keepw[w];
        if ((kw >> b) & 1u) {
            int rank = (int)wpref[w] + __popc(kw & ((1u << b) - 1u));
            if (rank < MAXBOX) s_sel[rank] = g_topk_idx[t];
        }
    }
    __syncthreads();

    int nk = s_nkeep;
    if (nk > MAXBOX) nk = MAXBOX;
    for (int e = t; e < MAXBOX * DET_DIM; e += 1024) {
        int r = e / DET_DIM;
        int c = e - r * DET_DIM;
        out[e] = (r < nk) ? det[(size_t)s_sel[r] * DET_DIM + c] : 0.0f;
    }
}

// ---------------- launch: SIX kernels ----------------
extern "C" void kernel_launch(void* const* d_in, const int* in_sizes, int n_in,
                              void* d_out, int out_size) {
    const float* boxes = (const float*)d_in[0];
    const float* cls   = (const float*)d_in[1];
    const float* det   = (const float*)d_in[2];
    float* out = (float*)d_out;

    cudaFuncSetAttribute((const void*)k7_scan,
                         cudaFuncAttributeMaxDynamicSharedMemorySize,
                         32 * TOPK * 4);

    k1_score<<<NBLK1, 256>>>(cls);
    k2_hist64<<<NPASS, PBLK>>>();
    k4_compact<<<NCBLK, 1024>>>();
    k5_rank<<<(CAP + 1023) / 1024, 1024>>>(boxes);
    k6_mask<<<NMBLK, PBLK>>>();
    k7_scan<<<1, 1024, 32 * TOPK * 4>>>(det, out);
}

// round 17
// speedup vs baseline: 1.3718x; 1.3718x over previous
#include <cuda_runtime.h>
#include <cstdint>

#define N_ANCH   300000
#define N_CLS    80
#define DET_DIM  85
#define TOPK     1000
#define MAXBOX   300
#define CAP      4096
#define NMS_THR  0.4f

#define NCH16    (N_ANCH / 16)          // 18750
#define NBLK1    ((NCH16 + 15) / 16)    // 1172 K1 blocks
#define NU4      (N_ANCH / 4)           // 75000 uint4 keys
#define PBLK     256
#define NPASS    ((NU4 + PBLK - 1) / PBLK)       // 293
#define NCBLK    ((NU4 + 1023) / 1024)           // 74
#define NMBLK    ((32 * TOPK + PBLK - 1) / PBLK) // 125

// ---------------- device scratch ----------------
__device__ unsigned int       g_scores[N_ANCH];
__device__ unsigned int       g_h1[256];     // bits[31:24]   (zeroed by K7)
__device__ unsigned int       g_h2[256];     // bits[23:16]|d1
__device__ unsigned int       g_h3[256];     // bits[15:8]|pre16
__device__ int                g_cand_cnt;
__device__ unsigned long long g_cand[CAP];
__device__ int                g_topk_idx[TOPK];
__device__ float4             g_boxk[TOPK];
__device__ unsigned int       g_maskmat[32 * TOPK];   // TRANSPOSED [colword][row]

__device__ __forceinline__ void aggInc(unsigned int* h, unsigned int bucket) {
    unsigned int am = __activemask();
    unsigned int peers = __match_any_sync(am, bucket);
    int leader = __ffs(peers) - 1;
    if ((threadIdx.x & 31) == leader) atomicAdd(&h[bucket], __popc(peers));
}

// 256-bin resolve (verified; callable with blockDim >= 256)
__device__ __forceinline__ void resolve256(const unsigned int* gh, unsigned int kth,
                                           unsigned int* shR,
                                           unsigned int* s_dig, unsigned int* s_kth) {
    int t = threadIdx.x;
    if (t < 256) shR[t] = gh[t];
    __syncthreads();
    for (int off = 1; off < 256; off <<= 1) {
        unsigned int v = 0, u = 0;
        if (t < 256) { v = shR[t]; u = (t + off < 256) ? shR[t + off] : 0u; }
        __syncthreads();
        if (t < 256) shR[t] = v + u;
        __syncthreads();
    }
    if (t < 256) {
        unsigned int e = (t < 255) ? shR[t + 1] : 0u;
        if (e < kth && shR[t] >= kth) { *s_dig = (unsigned int)t; *s_kth = kth - e; }
    }
    __syncthreads();
}

__device__ __forceinline__ float max20(const float4* r) {
    float a0 = fmaxf(fmaxf(r[0].x, r[0].y), fmaxf(r[0].z, r[0].w));
    float a1 = fmaxf(fmaxf(r[1].x, r[1].y), fmaxf(r[1].z, r[1].w));
    float a2 = fmaxf(fmaxf(r[2].x, r[2].y), fmaxf(r[2].z, r[2].w));
    float a3 = fmaxf(fmaxf(r[3].x, r[3].y), fmaxf(r[3].z, r[3].w));
    float a4 = fmaxf(fmaxf(r[4].x, r[4].y), fmaxf(r[4].z, r[4].w));
    return fmaxf(fmaxf(fmaxf(a0, a1), fmaxf(a2, a3)), a4);
}

// ===== K1: score/max (+ldcs) + hist bits[31:24] (R13 verified) =====
extern "C" __global__ void __launch_bounds__(256, 4)
k1_score(const float* __restrict__ cls) {
    __shared__ unsigned int shH[256];
    const int t = threadIdx.x, lane = t & 31, warp = t >> 5;
    shH[t] = 0u;
    __syncthreads();
    const float4* gp = (const float4*)cls;
    const int p = lane & 3, a = lane >> 2;
    const int cend = min((int)((blockIdx.x + 1) * 16), NCH16);
    for (int chunk = blockIdx.x * 16 + warp; chunk < cend; chunk += 8) {
        const size_t b0 = (size_t)chunk * (16 * 20);
        float4 r0[5], r1[5];
        const size_t o0 = b0 + a * 20 + p;
        const size_t o1 = o0 + 160;
#pragma unroll
        for (int j = 0; j < 5; j++) r0[j] = __ldcs(&gp[o0 + 4 * j]);
#pragma unroll
        for (int j = 0; j < 5; j++) r1[j] = __ldcs(&gp[o1 + 4 * j]);
        float m0 = max20(r0), m1 = max20(r1);
        m0 = fmaxf(m0, __shfl_xor_sync(0xFFFFFFFFu, m0, 1));
        m0 = fmaxf(m0, __shfl_xor_sync(0xFFFFFFFFu, m0, 2));
        m1 = fmaxf(m1, __shfl_xor_sync(0xFFFFFFFFu, m1, 1));
        m1 = fmaxf(m1, __shfl_xor_sync(0xFFFFFFFFu, m1, 2));
        unsigned int k0 = __float_as_uint(m0);   // scores >= 0 -> monotonic bits
        unsigned int k1 = __float_as_uint(m1);
        if (p == 0) {
            int A0 = chunk * 16;
            g_scores[A0 + a]     = k0;
            g_scores[A0 + 8 + a] = k1;
            aggInc(shH, k0 >> 24);
            aggInc(shH, k1 >> 24);
        }
    }
    __syncthreads();
    if (shH[t]) atomicAdd(&g_h1[t], shH[t]);
}

// ===== K2: hist bits[23:16] restricted to d1 (R13 verified) =====
extern "C" __global__ void __launch_bounds__(PBLK)
k2_hist2() {
    __shared__ unsigned int shR[256];
    __shared__ unsigned int shH[256];
    __shared__ unsigned int s_d1, s_k1;
    int t = threadIdx.x;
    shH[t] = 0u;
    resolve256(g_h1, TOPK, shR, &s_d1, &s_k1);
    unsigned int d1 = s_d1;
    int i = blockIdx.x * PBLK + t;
    if (i < NU4) {
        uint4 k = ((const uint4*)g_scores)[i];
        if ((k.x >> 24) == d1) aggInc(shH, (k.x >> 16) & 255u);
        if ((k.y >> 24) == d1) aggInc(shH, (k.y >> 16) & 255u);
        if ((k.z >> 24) == d1) aggInc(shH, (k.z >> 16) & 255u);
        if ((k.w >> 24) == d1) aggInc(shH, (k.w >> 16) & 255u);
    }
    __syncthreads();
    if (shH[t]) atomicAdd(&g_h2[t], shH[t]);
}

// ===== K3: hist bits[15:8] restricted to pre16 (R13 verified) =====
extern "C" __global__ void __launch_bounds__(PBLK)
k3_hist3() {
    __shared__ unsigned int shR[256];
    __shared__ unsigned int shH[256];
    __shared__ unsigned int s_d1, s_k1, s_d2, s_k2;
    int t = threadIdx.x;
    shH[t] = 0u;
    resolve256(g_h1, TOPK, shR, &s_d1, &s_k1);
    resolve256(g_h2, s_k1, shR, &s_d2, &s_k2);
    unsigned int pre16 = (s_d1 << 8) | s_d2;
    int i = blockIdx.x * PBLK + t;
    if (i < NU4) {
        uint4 k = ((const uint4*)g_scores)[i];
        if ((k.x >> 16) == pre16) aggInc(shH, (k.x >> 8) & 255u);
        if ((k.y >> 16) == pre16) aggInc(shH, (k.y >> 8) & 255u);
        if ((k.z >> 16) == pre16) aggInc(shH, (k.z >> 8) & 255u);
        if ((k.w >> 16) == pre16) aggInc(shH, (k.w >> 8) & 255u);
    }
    __syncthreads();
    if (shH[t]) atomicAdd(&g_h3[t], shH[t]);
}

// ===== K4: resolve threshold + warp-aggregated compact (1024-thr blocks) =====
extern "C" __global__ void __launch_bounds__(1024)
k4_compact() {
    __shared__ unsigned int shR[256];
    __shared__ unsigned int s_d1, s_k1, s_d2, s_k2, s_d3, s_k3;
    int t = threadIdx.x;
    resolve256(g_h1, TOPK, shR, &s_d1, &s_k1);
    resolve256(g_h2, s_k1, shR, &s_d2, &s_k2);
    resolve256(g_h3, s_k2, shR, &s_d3, &s_k3);
    unsigned int T = (s_d1 << 24) | (s_d2 << 16) | (s_d3 << 8);
    int i = blockIdx.x * 1024 + t;
    if (i < NU4) {
        uint4 k = ((const uint4*)g_scores)[i];
        unsigned int bi = (unsigned int)(i * 4);
#pragma unroll
        for (int c = 0; c < 4; c++) {
            unsigned int key = (c == 0) ? k.x : (c == 1) ? k.y : (c == 2) ? k.z : k.w;
            bool p = (key >= T);
            unsigned int am = __activemask();
            unsigned int bal = __ballot_sync(am, p);
            if (p) {
                int lane = t & 31;
                int leader = __ffs(bal) - 1;
                int base = 0;
                if (lane == leader) base = atomicAdd(&g_cand_cnt, __popc(bal));
                base = __shfl_sync(bal, base, leader);
                int slot = base + __popc(bal & ((1u << lane) - 1u));
                if (slot < CAP)
                    g_cand[slot] = ((unsigned long long)key << 32) |
                                   (unsigned long long)(0xFFFFFFFFu - (bi + c));
            }
        }
    }
}

// ===== K5: ILP rank-select (8-way unroll, zero-padded) + box gather =====
extern "C" __global__ void __launch_bounds__(1024)
k5_rank(const float* __restrict__ boxes) {
    __shared__ unsigned long long sc[CAP + 8];
    int t = threadIdx.x;
    int cnt = g_cand_cnt;
    if (cnt > CAP) cnt = CAP;
    int cpad = (cnt + 7) & ~7;
    for (int i = t; i < cpad; i += 1024)
        sc[i] = (i < cnt) ? g_cand[i] : 0ull;   // 0 pad: 0 > key never true
    __syncthreads();
    int i = blockIdx.x * 1024 + t;
    if (i < cnt) {
        unsigned long long key = sc[i];
        int r0 = 0, r1 = 0, r2 = 0, r3 = 0, r4 = 0, r5 = 0, r6 = 0, r7 = 0;
        for (int j = 0; j < cpad; j += 8) {
            r0 += (sc[j    ] > key); r1 += (sc[j + 1] > key);
            r2 += (sc[j + 2] > key); r3 += (sc[j + 3] > key);
            r4 += (sc[j + 4] > key); r5 += (sc[j + 5] > key);
            r6 += (sc[j + 6] > key); r7 += (sc[j + 7] > key);
        }
        int rank = ((r0 + r1) + (r2 + r3)) + ((r4 + r5) + (r6 + r7));
        if (rank < TOPK) {
            int idx = (int)(0xFFFFFFFFu - (unsigned int)key);
            g_topk_idx[rank] = idx;
            g_boxk[rank] = ((const float4*)boxes)[idx];
        }
    }
}

// ===== K6: IoU bitmask, transposed (bit-exact fp32, verified) =====
extern "C" __global__ void __launch_bounds__(PBLK)
k6_mask() {
    int w = blockIdx.x * PBLK + threadIdx.x;
    if (w >= 32 * TOPK) return;
    int wj = w / TOPK;
    int i  = w - wj * TOPK;
    float4 bi = g_boxk[i];
    float ai = __fmul_rn(__fsub_rn(bi.z, bi.x), __fsub_rn(bi.w, bi.y));
    unsigned int bits = 0u;
    int j0 = wj * 32;
#pragma unroll 8
    for (int tt = 0; tt < 32; tt++) {
        int j = j0 + tt;
        if (j < TOPK) {
            float4 bj = g_boxk[j];
            float aj = __fmul_rn(__fsub_rn(bj.z, bj.x), __fsub_rn(bj.w, bj.y));
            float ih = fmaxf(__fsub_rn(fminf(bi.z, bj.z), fmaxf(bi.x, bj.x)), 0.0f);
            float iw = fmaxf(__fsub_rn(fminf(bi.w, bj.w), fmaxf(bi.y, bj.y)), 0.0f);
            float inter = __fmul_rn(ih, iw);
            float denom = __fadd_rn(__fsub_rn(__fadd_rn(ai, aj), inter), 1e-8f);
            float iou = __fdiv_rn(inter, denom);
            if (iou > NMS_THR) bits |= (1u << tt);
        }
    }
    g_maskmat[w] = bits;
}

// ===== K7: single-block greedy keep-scan + output + state cleanup (verified) =====
extern "C" __global__ void __launch_bounds__(1024)
k7_scan(const float* __restrict__ det, float* __restrict__ out) {
    extern __shared__ unsigned int smask[];   // 32*TOPK words
    __shared__ unsigned int keepw[32], wpref[32];
    __shared__ int s_sel[MAXBOX];
    __shared__ int s_nkeep;
    const int t = threadIdx.x, lane = t & 31;
    for (int i = t; i < 32 * TOPK; i += 1024) smask[i] = g_maskmat[i];
    if (t < 256) { g_h1[t] = 0u; g_h2[t] = 0u; g_h3[t] = 0u; }
    if (t == 0) g_cand_cnt = 0;
    __syncthreads();

    if (t < 32) {
        for (int tile = 0; tile < 32; tile++) {
            int r = tile * 32 + lane;
            int nrows = TOPK - tile * 32; if (nrows > 32) nrows = 32;
            bool base_i = false;
            unsigned int wt_i = 0u;
            if (r < TOPK) {
                for (int w = 0; w < tile; w++)
                    base_i |= (keepw[w] & smask[w * TOPK + r]) != 0u;
                wt_i = smask[tile * TOPK + r];
            }
            unsigned int bases = __ballot_sync(0xFFFFFFFFu, base_i);
            unsigned int keep_tile = 0u;
#pragma unroll
            for (int rr = 0; rr < 32; rr++) {
                unsigned int word_r = __shfl_sync(0xFFFFFFFFu, wt_i, rr);
                bool sup = ((bases >> rr) & 1u) ||
                           ((keep_tile & word_r & ((1u << rr) - 1u)) != 0u);
                if (!sup && rr < nrows) keep_tile |= 1u << rr;
            }
            if (lane == 0) keepw[tile] = keep_tile;
            __syncwarp();
        }
        unsigned int kw = keepw[lane];
        unsigned int pc = __popc(kw);
        unsigned int inc = pc;
        for (int off = 1; off < 32; off <<= 1) {
            unsigned int v = __shfl_up_sync(0xFFFFFFFFu, inc, off);
            if (lane >= off) inc += v;
        }
        wpref[lane] = inc - pc;
        if (lane == 31) s_nkeep = (int)inc;
    }
    __syncthreads();

    if (t < TOPK) {
        int w = t >> 5, b = t & 31;
        unsigned int kw = keepw[w];
        if ((kw >> b) & 1u) {
            int rank = (int)wpref[w] + __popc(kw & ((1u << b) - 1u));
            if (rank < MAXBOX) s_sel[rank] = g_topk_idx[t];
        }
    }
    __syncthreads();

    int nk = s_nkeep;
    if (nk > MAXBOX) nk = MAXBOX;
    for (int e = t; e < MAXBOX * DET_DIM; e += 1024) {
        int r = e / DET_DIM;
        int c = e - r * DET_DIM;
        out[e] = (r < nk) ? det[(size_t)s_sel[r] * DET_DIM + c] : 0.0f;
    }
}

// ---------------- launch: SEVEN kernels ----------------
extern "C" void kernel_launch(void* const* d_in, const int* in_sizes, int n_in,
                              void* d_out, int out_size) {
    const float* boxes = (const float*)d_in[0];
    const float* cls   = (const float*)d_in[1];
    const float* det   = (const float*)d_in[2];
    float* out = (float*)d_out;

    cudaFuncSetAttribute((const void*)k7_scan,
                         cudaFuncAttributeMaxDynamicSharedMemorySize,
                         32 * TOPK * 4);

    k1_score<<<NBLK1, 256>>>(cls);
    k2_hist2<<<NPASS, PBLK>>>();
    k3_hist3<<<NPASS, PBLK>>>();
    k4_compact<<<NCBLK, 1024>>>();
    k5_rank<<<(CAP + 1023) / 1024, 1024>>>(boxes);
    k6_mask<<<NMBLK, PBLK>>>();
    k7_scan<<<1, 1024, 32 * TOPK * 4>>>(det, out);
}